// round 2
// baseline (speedup 1.0000x reference)
#include <cuda_runtime.h>
#include <cstdint>

// Problem constants
constexpr int BATCH = 8;
constexpr int CIN   = 256;     // channels (K dim of GEMMs, also out channels)
constexpr int MM    = 16384;   // H*W
constexpr int NMT   = 256;     // MM / 64 m-tiles per batch

// Scratch (static device arrays: allowed; no atomics -> deterministic)
__device__ float g_Apart[BATCH * NMT * 4096];   // per-(b,mtile) partial A: [16 heads][16 d][16 e]
__device__ float g_QKpart[BATCH * NMT * 512];   // per-(b,mtile) partial qsum[256], ksum[256]
__device__ float g_W2[BATCH * 256 * 256];       // folded weight: out = W2[b] @ x[b]

__device__ __forceinline__ uint32_t f2tf32(float x){
    uint32_t r; asm("cvt.rna.tf32.f32 %0, %1;" : "=r"(r) : "f"(x)); return r;
}
__device__ __forceinline__ void mma8(float c[4], const uint32_t a[4], const uint32_t b[2]){
    asm volatile("mma.sync.aligned.m16n8k8.row.col.f32.tf32.tf32.f32 "
        "{%0,%1,%2,%3},{%4,%5,%6,%7},{%8,%9},{%0,%1,%2,%3};"
        : "+f"(c[0]), "+f"(c[1]), "+f"(c[2]), "+f"(c[3])
        : "r"(a[0]), "r"(a[1]), "r"(a[2]), "r"(a[3]), "r"(b[0]), "r"(b[1]));
}
__device__ __forceinline__ void cp16(uint32_t dst, const void* src){
    asm volatile("cp.async.cg.shared.global [%0], [%1], 16;" :: "r"(dst), "l"(src));
}
__device__ __forceinline__ void cpcommit(){ asm volatile("cp.async.commit_group;"); }
__device__ __forceinline__ float elu1(float x){ return x > 0.f ? x + 1.f : __expf(x); }

// ---------------------------------------------------------------------------
// Pass 1: Q,K projection GEMMs (tf32 MMA) + fused elu, A / qsum / ksum partial
// reductions. CTA = 256 channels x 64 m, K=256. 512 threads (16 warps, 32x32
// warp tiles x 2 matrices).
// smem (floats): stage region Wq[2][256][20]@0, Wk@10240, Xs[2][16][72]@20480;
// epilogue tiles[16 warps][2][32][36]@0 (reuse); Asm[4096]@36864; qsS@40960;
// ksS@41216. Total 41472 floats = 165888 B dynamic smem.
// ---------------------------------------------------------------------------
__global__ void __launch_bounds__(512, 1) pass1_kernel(
    const float* __restrict__ x, const float* __restrict__ wq, const float* __restrict__ wk)
{
    extern __shared__ float sm[];
    const int tid  = threadIdx.x;
    const int warp = tid >> 5, lane = tid & 31;
    const int g = lane >> 2, t4 = lane & 3;
    const int cw = warp >> 1, mw = warp & 1;
    const int c0 = cw * 32, nbase = mw * 32;
    const int mt = blockIdx.x, b = blockIdx.y;
    const int m0 = mt * 64;

    float* Wqs   = sm;                 // [2][256][20]
    float* Wks   = sm + 10240;         // [2][256][20]
    float* Xss   = sm + 20480;         // [2][16][72]
    float* tiles = sm;                 // epilogue reuse: [16][2][32][36]
    float* Asm   = sm + 36864;         // [4096]
    float* qsS   = sm + 40960;         // [256]
    float* ksS   = sm + 41216;         // [256]

    // zero reduction buffers (region untouched by main loop)
    for (int i = tid; i < 4608; i += 512) sm[36864 + i] = 0.f;

    const float* xb = x + (size_t)b * ((size_t)CIN * MM);
    const uint32_t smbase = (uint32_t)__cvta_generic_to_shared(sm);

    auto fill = [&](int st, int k0){
        #pragma unroll
        for (int r = 0; r < 2; ++r){
            int chunk = tid + r * 512;
            int row = chunk >> 2, c4 = chunk & 3;
            cp16(smbase + (uint32_t)((st * 5120 + row * 20 + c4 * 4) * 4),
                 wq + row * 256 + k0 + c4 * 4);
            cp16(smbase + (uint32_t)((10240 + st * 5120 + row * 20 + c4 * 4) * 4),
                 wk + row * 256 + k0 + c4 * 4);
        }
        if (tid < 256){
            int row = tid >> 4, j = tid & 15;
            cp16(smbase + (uint32_t)((20480 + st * 1152 + row * 72 + j * 4) * 4),
                 xb + (size_t)(k0 + row) * MM + m0 + j * 4);
        }
        cpcommit();
    };

    float qacc[2][4][4], kacc[2][4][4];
    #pragma unroll
    for (int i = 0; i < 2; ++i)
        #pragma unroll
        for (int j = 0; j < 4; ++j)
            #pragma unroll
            for (int e = 0; e < 4; ++e){ qacc[i][j][e] = 0.f; kacc[i][j][e] = 0.f; }

    fill(0, 0);

    for (int kt = 0; kt < 16; ++kt){
        int cur = kt & 1;
        if (kt + 1 < 16){
            fill(cur ^ 1, (kt + 1) * 16);
            asm volatile("cp.async.wait_group 1;");
        } else {
            asm volatile("cp.async.wait_group 0;");
        }
        __syncthreads();

        const float* Wq_st = Wqs + cur * 5120;
        const float* Wk_st = Wks + cur * 5120;
        const float* X_st  = Xss + cur * 1152;

        #pragma unroll
        for (int kk = 0; kk < 16; kk += 8){
            uint32_t aq[2][4], ak[2][4], bx[4][2];
            #pragma unroll
            for (int i = 0; i < 2; ++i){
                int r = c0 + i * 16 + g;
                aq[i][0] = f2tf32(Wq_st[r * 20 + kk + t4]);
                aq[i][1] = f2tf32(Wq_st[(r + 8) * 20 + kk + t4]);
                aq[i][2] = f2tf32(Wq_st[r * 20 + kk + t4 + 4]);
                aq[i][3] = f2tf32(Wq_st[(r + 8) * 20 + kk + t4 + 4]);
                ak[i][0] = f2tf32(Wk_st[r * 20 + kk + t4]);
                ak[i][1] = f2tf32(Wk_st[(r + 8) * 20 + kk + t4]);
                ak[i][2] = f2tf32(Wk_st[r * 20 + kk + t4 + 4]);
                ak[i][3] = f2tf32(Wk_st[(r + 8) * 20 + kk + t4 + 4]);
            }
            #pragma unroll
            for (int j = 0; j < 4; ++j){
                int n = nbase + j * 8 + g;
                bx[j][0] = f2tf32(X_st[(kk + t4) * 72 + n]);
                bx[j][1] = f2tf32(X_st[(kk + t4 + 4) * 72 + n]);
            }
            #pragma unroll
            for (int i = 0; i < 2; ++i)
                #pragma unroll
                for (int j = 0; j < 4; ++j){
                    mma8(qacc[i][j], aq[i], bx[j]);
                    mma8(kacc[i][j], ak[i], bx[j]);
                }
        }
        __syncthreads();
    }

    // ---- epilogue: elu+1, stage tiles, reduce A / qsum / ksum ----
    float* qs = tiles + warp * 2304;   // [32][36]
    float* ks = qs + 1152;
    #pragma unroll
    for (int i = 0; i < 2; ++i)
        #pragma unroll
        for (int j = 0; j < 4; ++j){
            int r0 = i * 16 + g, r1 = r0 + 8;
            int cA = j * 8 + t4 * 2;
            *(float2*)&qs[r0 * 36 + cA] = make_float2(elu1(qacc[i][j][0]), elu1(qacc[i][j][1]));
            *(float2*)&qs[r1 * 36 + cA] = make_float2(elu1(qacc[i][j][2]), elu1(qacc[i][j][3]));
            *(float2*)&ks[r0 * 36 + cA] = make_float2(elu1(kacc[i][j][0]), elu1(kacc[i][j][1]));
            *(float2*)&ks[r1 * 36 + cA] = make_float2(elu1(kacc[i][j][2]), elu1(kacc[i][j][3]));
        }
    __syncwarp();

    // per-row sums over this warp's 32 m-columns
    {
        const float4* qr = (const float4*)&qs[lane * 36];
        const float4* kr = (const float4*)&ks[lane * 36];
        float sq = 0.f, sk = 0.f;
        #pragma unroll
        for (int m4 = 0; m4 < 8; ++m4){
            float4 a = qr[m4]; sq += a.x + a.y + a.z + a.w;
            float4 c2 = kr[m4]; sk += c2.x + c2.y + c2.z + c2.w;
        }
        atomicAdd(&qsS[c0 + lane], sq);   // smem atomic, 2 warps/addr
        atomicAdd(&ksS[c0 + lane], sk);
    }

    // A partials: this warp covers 2 heads; 512 (hh,d,e) pairs over m=32
    #pragma unroll 4
    for (int p = 0; p < 16; ++p){
        int idx = p * 32 + lane;
        int hh = idx >> 8, rem = idx & 255;
        int d = rem >> 4, e = rem & 15;
        const float4* qrow = (const float4*)&qs[(hh * 16 + d) * 36];
        const float4* krow = (const float4*)&ks[(hh * 16 + e) * 36];
        float acc = 0.f;
        #pragma unroll
        for (int m4 = 0; m4 < 8; ++m4){
            float4 a = qrow[m4], v = krow[m4];
            acc += a.x * v.x + a.y * v.y + a.z * v.z + a.w * v.w;
        }
        atomicAdd(&Asm[(cw * 2 + hh) * 256 + rem], acc);
    }
    __syncthreads();

    // write per-CTA partials (no global atomics)
    {
        size_t abase = ((size_t)(b * NMT + mt)) * 4096;
        for (int e2 = tid; e2 < 4096; e2 += 512) g_Apart[abase + e2] = Asm[e2];
        size_t qb = ((size_t)(b * NMT + mt)) * 512;
        g_QKpart[qb + tid] = (tid < 256) ? qsS[tid] : ksS[tid - 256];
    }
}

// ---------------------------------------------------------------------------
// Pass 2: reduce partials -> A[b], qsum, ksum; z[b,h]; W2[b] = diag-quirk z * A @ wv
// NOTE the reference broadcasting quirk: scale is z[b, d] (dh index), not z[b, h].
// ---------------------------------------------------------------------------
__global__ void pass2_kernel(const float* __restrict__ wv)
{
    __shared__ float As[4096];
    __shared__ float Qs[256], Ks[256], Z[16];
    const int b = blockIdx.x, tid = threadIdx.x;  // 512 threads

    for (int e = tid; e < 4096; e += 512){
        float s = 0.f;
        const float* p = g_Apart + (size_t)b * NMT * 4096 + e;
        for (int mt2 = 0; mt2 < NMT; ++mt2) s += p[(size_t)mt2 * 4096];
        As[e] = s;
    }
    {
        float s = 0.f;
        const float* p = g_QKpart + (size_t)b * NMT * 512 + tid;
        for (int mt2 = 0; mt2 < NMT; ++mt2) s += p[mt2 * 512];
        if (tid < 256) Qs[tid] = s; else Ks[tid - 256] = s;
    }
    __syncthreads();
    if (tid < 16){
        float dsum = 0.f;
        #pragma unroll
        for (int dd = 0; dd < 16; ++dd) dsum += Qs[tid * 16 + dd] * Ks[tid * 16 + dd];
        Z[tid] = 1.f / (dsum + 1e-6f);
    }
    __syncthreads();

    for (int idx = tid; idx < 65536; idx += 512){
        int c = idx >> 8, k = idx & 255;
        int h = c >> 4, d = c & 15;
        const float* arow = As + (h * 16 + d) * 16;
        float acc = 0.f;
        #pragma unroll
        for (int e = 0; e < 16; ++e) acc += arow[e] * wv[(h * 16 + e) * 256 + k];
        g_W2[((size_t)b * 256 + c) * 256 + k] = Z[d] * acc;   // z indexed by d (quirk)
    }
}

// ---------------------------------------------------------------------------
// Pass 3: out[b] = W2[b] @ x[b]  (tf32 MMA), direct fp32 output writes.
// smem: W2s[2][256][20]@0 (10240 fl), Xs[2][16][72]@10240 -> 50176 B dynamic.
// ---------------------------------------------------------------------------
__global__ void __launch_bounds__(512, 1) pass3_kernel(
    const float* __restrict__ x, float* __restrict__ out)
{
    extern __shared__ float sm[];
    const int tid  = threadIdx.x;
    const int warp = tid >> 5, lane = tid & 31;
    const int g = lane >> 2, t4 = lane & 3;
    const int cw = warp >> 1, mw = warp & 1;
    const int c0 = cw * 32, nbase = mw * 32;
    const int mt = blockIdx.x, b = blockIdx.y;
    const int m0 = mt * 64;

    float* Ws  = sm;            // [2][256][20]
    float* Xss = sm + 10240;    // [2][16][72]

    const float* w2 = g_W2 + (size_t)b * 65536;
    const float* xb = x + (size_t)b * ((size_t)CIN * MM);
    const uint32_t smbase = (uint32_t)__cvta_generic_to_shared(sm);

    auto fill = [&](int st, int k0){
        #pragma unroll
        for (int r = 0; r < 2; ++r){
            int chunk = tid + r * 512;
            int row = chunk >> 2, c4 = chunk & 3;
            cp16(smbase + (uint32_t)((st * 5120 + row * 20 + c4 * 4) * 4),
                 w2 + row * 256 + k0 + c4 * 4);
        }
        if (tid < 256){
            int row = tid >> 4, j = tid & 15;
            cp16(smbase + (uint32_t)((10240 + st * 1152 + row * 72 + j * 4) * 4),
                 xb + (size_t)(k0 + row) * MM + m0 + j * 4);
        }
        cpcommit();
    };

    float pacc[2][4][4];
    #pragma unroll
    for (int i = 0; i < 2; ++i)
        #pragma unroll
        for (int j = 0; j < 4; ++j)
            #pragma unroll
            for (int e = 0; e < 4; ++e) pacc[i][j][e] = 0.f;

    fill(0, 0);

    for (int kt = 0; kt < 16; ++kt){
        int cur = kt & 1;
        if (kt + 1 < 16){
            fill(cur ^ 1, (kt + 1) * 16);
            asm volatile("cp.async.wait_group 1;");
        } else {
            asm volatile("cp.async.wait_group 0;");
        }
        __syncthreads();

        const float* W_st = Ws + cur * 5120;
        const float* X_st = Xss + cur * 1152;

        #pragma unroll
        for (int kk = 0; kk < 16; kk += 8){
            uint32_t aw[2][4], bx[4][2];
            #pragma unroll
            for (int i = 0; i < 2; ++i){
                int r = c0 + i * 16 + g;
                aw[i][0] = f2tf32(W_st[r * 20 + kk + t4]);
                aw[i][1] = f2tf32(W_st[(r + 8) * 20 + kk + t4]);
                aw[i][2] = f2tf32(W_st[r * 20 + kk + t4 + 4]);
                aw[i][3] = f2tf32(W_st[(r + 8) * 20 + kk + t4 + 4]);
            }
            #pragma unroll
            for (int j = 0; j < 4; ++j){
                int n = nbase + j * 8 + g;
                bx[j][0] = f2tf32(X_st[(kk + t4) * 72 + n]);
                bx[j][1] = f2tf32(X_st[(kk + t4 + 4) * 72 + n]);
            }
            #pragma unroll
            for (int i = 0; i < 2; ++i)
                #pragma unroll
                for (int j = 0; j < 4; ++j)
                    mma8(pacc[i][j], aw[i], bx[j]);
        }
        __syncthreads();
    }

    // write out: out[b, c, m]
    #pragma unroll
    for (int i = 0; i < 2; ++i){
        size_t row0 = ((size_t)b * 256 + c0 + i * 16 + g) * MM + m0 + nbase;
        size_t row1 = row0 + (size_t)8 * MM;
        #pragma unroll
        for (int j = 0; j < 4; ++j){
            *(float2*)&out[row0 + j * 8 + t4 * 2] = make_float2(pacc[i][j][0], pacc[i][j][1]);
            *(float2*)&out[row1 + j * 8 + t4 * 2] = make_float2(pacc[i][j][2], pacc[i][j][3]);
        }
    }
}

extern "C" void kernel_launch(void* const* d_in, const int* in_sizes, int n_in,
                              void* d_out, int out_size)
{
    const float* x  = (const float*)d_in[0];
    const float* wq = (const float*)d_in[1];
    const float* wk = (const float*)d_in[2];
    const float* wv = (const float*)d_in[3];
    float* out = (float*)d_out;

    cudaFuncSetAttribute(pass1_kernel, cudaFuncAttributeMaxDynamicSharedMemorySize, 165888);
    cudaFuncSetAttribute(pass3_kernel, cudaFuncAttributeMaxDynamicSharedMemorySize, 50176);

    pass1_kernel<<<dim3(NMT, BATCH), 512, 165888>>>(x, wq, wk);
    pass2_kernel<<<BATCH, 512>>>(wv);
    pass3_kernel<<<dim3(NMT, BATCH), 512, 50176>>>(x, out);
}

// round 5
// speedup vs baseline: 1.2094x; 1.2094x over previous
#include <cuda_runtime.h>
#include <cstdint>

// Problem constants
constexpr int BATCH = 8;
constexpr int CIN   = 256;     // channels (K dim of GEMMs, also out channels)
constexpr int MM    = 16384;   // H*W
constexpr int NMT   = 256;     // MM / 64 m-tiles per batch (pass1)
constexpr int NMT3  = 128;     // MM / 128 m-tiles per batch (pass3)

// Scratch (static device arrays: allowed; no global atomics -> deterministic)
__device__ float    g_Apart[BATCH * NMT * 4096];   // per-(b,mtile) partial A
__device__ float    g_QKpart[BATCH * NMT * 512];   // per-(b,mtile) qsum/ksum partials
__device__ uint32_t g_WqP[65536];                  // wq, tf32 bits, fragment-permuted
__device__ uint32_t g_WkP[65536];                  // wk, tf32 bits, fragment-permuted
__device__ uint32_t g_W2P[BATCH * 65536];          // folded weight, tf32 bits, permuted

__device__ __forceinline__ uint32_t f2tf32(float x){
    uint32_t r; asm("cvt.rna.tf32.f32 %0, %1;" : "=r"(r) : "f"(x)); return r;
}
__device__ __forceinline__ void mma8(float c[4], const uint32_t a[4], const uint32_t b[2]){
    asm volatile("mma.sync.aligned.m16n8k8.row.col.f32.tf32.tf32.f32 "
        "{%0,%1,%2,%3},{%4,%5,%6,%7},{%8,%9},{%0,%1,%2,%3};"
        : "+f"(c[0]), "+f"(c[1]), "+f"(c[2]), "+f"(c[3])
        : "r"(a[0]), "r"(a[1]), "r"(a[2]), "r"(a[3]), "r"(b[0]), "r"(b[1]));
}
__device__ __forceinline__ void cp16(uint32_t dst, const void* src){
    asm volatile("cp.async.cg.shared.global [%0], [%1], 16;" :: "r"(dst), "l"(src));
}
__device__ __forceinline__ void cpcommit(){ asm volatile("cp.async.commit_group;"); }
__device__ __forceinline__ float elu1(float x){ return x > 0.f ? x + 1.f : __expf(x); }

// Fragment-permuted weight layout (per 256x256 matrix, 65536 entries):
//   pos = ((((kt*8 + cw)*2 + i)*2 + kk8)*32 + lane)*4 + e
//   g=lane>>2, t4=lane&3, hi=e&1, half=e>>1
//   r = cw*32 + i*16 + hi*8 + g ;  k = kt*16 + kk8*8 + half*4 + t4
// Within a kt-block (4096 words): cw stride = 512, i stride = 256, kk8 stride = 128.
// A warp's m16n8k8 A-fragment (a0..a3) is one contiguous float4 per lane.

// ---------------------------------------------------------------------------
// Prep: convert wq/wk (fp32 row-major [256][256]) -> tf32 bits, permuted.
// ---------------------------------------------------------------------------
__global__ void prep_w_kernel(const float* __restrict__ wq, const float* __restrict__ wk)
{
    int idx = blockIdx.x * 512 + threadIdx.x;      // grid 256 * 512 = 131072
    int mat = idx >> 16;
    int pos = idx & 65535;
    int e    = pos & 3;
    int lane = (pos >> 2) & 31;
    int kk8  = (pos >> 7) & 1;
    int i    = (pos >> 8) & 1;
    int cw   = (pos >> 9) & 7;
    int kt   = pos >> 12;
    int g = lane >> 2, t4 = lane & 3;
    int hi = e & 1, half = e >> 1;
    int r = cw * 32 + i * 16 + hi * 8 + g;
    int k = kt * 16 + kk8 * 8 + half * 4 + t4;
    const float* w = mat ? wk : wq;
    uint32_t* dst  = mat ? g_WkP : g_WqP;
    dst[pos] = f2tf32(w[r * 256 + k]);
}

// ---------------------------------------------------------------------------
// Pass 1: Q,K projection GEMMs (tf32 MMA, permuted weight fragments) + fused
// elu, A / qsum / ksum partial reductions. CTA = 256c x 64m, 512 threads.
// smem(floats): WqS[2][4096]@0, WkS[2][4096]@8192, XS[2][16][72]@16384 (main)
//               tiles[16][2304]@0 (epilogue reuse), Asm@36864, qsS@40960,
//               ksS@41216 -> 41472 fl = 165888 B.
// ---------------------------------------------------------------------------
__global__ void __launch_bounds__(512, 1) pass1_kernel(const float* __restrict__ x)
{
    extern __shared__ float sm[];
    const int tid  = threadIdx.x;
    const int warp = tid >> 5, lane = tid & 31;
    const int g = lane >> 2, t4 = lane & 3;
    const int cw = warp >> 1, mw = warp & 1;
    const int c0 = cw * 32, nbase = mw * 32;
    const int mt = blockIdx.x, b = blockIdx.y;
    const int m0 = mt * 64;

    float* Xss   = sm + 16384;         // [2][16][72]
    float* tiles = sm;                 // epilogue reuse
    float* Asm   = sm + 36864;
    float* qsS   = sm + 40960;
    float* ksS   = sm + 41216;

    for (int i = tid; i < 4608; i += 512) sm[36864 + i] = 0.f;

    const float* xb = x + (size_t)b * ((size_t)CIN * MM);
    const uint32_t smbase = (uint32_t)__cvta_generic_to_shared(sm);

    auto fill = [&](int st, int kt){
        const uint32_t* wqsrc = g_WqP + kt * 4096;
        const uint32_t* wksrc = g_WkP + kt * 4096;
        #pragma unroll
        for (int r = 0; r < 2; ++r){
            int chunk = tid + r * 512;       // 1024 x float4 per matrix
            cp16(smbase + (uint32_t)((st * 4096 + chunk * 4) * 4), wqsrc + chunk * 4);
            cp16(smbase + (uint32_t)((8192 + st * 4096 + chunk * 4) * 4), wksrc + chunk * 4);
        }
        if (tid < 256){
            int row = tid >> 4, j = tid & 15;
            cp16(smbase + (uint32_t)((16384 + st * 1152 + row * 72 + j * 4) * 4),
                 xb + (size_t)(kt * 16 + row) * MM + m0 + j * 4);
        }
        cpcommit();
    };

    float qacc[2][4][4], kacc[2][4][4];
    #pragma unroll
    for (int i = 0; i < 2; ++i)
        #pragma unroll
        for (int j = 0; j < 4; ++j)
            #pragma unroll
            for (int e = 0; e < 4; ++e){ qacc[i][j][e] = 0.f; kacc[i][j][e] = 0.f; }

    fill(0, 0);

    for (int kt = 0; kt < 16; ++kt){
        int cur = kt & 1;
        if (kt + 1 < 16){
            fill(cur ^ 1, kt + 1);
            asm volatile("cp.async.wait_group 1;");
        } else {
            asm volatile("cp.async.wait_group 0;");
        }
        __syncthreads();

        const float* X_st = Xss + cur * 1152;
        // FIXED: cw stride within a 4096-word stage is 512 (was 1024 -> OOB garbage)
        const uint32_t wbase = cur * 4096 + cw * 512 + lane * 4;

        #pragma unroll
        for (int kk8 = 0; kk8 < 2; ++kk8){
            int kk = kk8 * 8;
            uint32_t aq[2][4], ak[2][4], bx[4][2];
            #pragma unroll
            for (int i = 0; i < 2; ++i){
                uint32_t off = wbase + (uint32_t)((i * 2 + kk8) * 128);
                *(uint4*)aq[i] = *(const uint4*)((const uint32_t*)sm + off);
                *(uint4*)ak[i] = *(const uint4*)((const uint32_t*)sm + 8192 + off);
            }
            #pragma unroll
            for (int j = 0; j < 4; ++j){
                int n = nbase + j * 8 + g;
                bx[j][0] = f2tf32(X_st[(kk + t4) * 72 + n]);
                bx[j][1] = f2tf32(X_st[(kk + t4 + 4) * 72 + n]);
            }
            #pragma unroll
            for (int i = 0; i < 2; ++i)
                #pragma unroll
                for (int j = 0; j < 4; ++j){
                    mma8(qacc[i][j], aq[i], bx[j]);
                    mma8(kacc[i][j], ak[i], bx[j]);
                }
        }
        __syncthreads();
    }

    // ---- epilogue: elu+1, stage tiles, reduce A / qsum / ksum ----
    float* qs = tiles + warp * 2304;   // [32][36]
    float* ks = qs + 1152;
    #pragma unroll
    for (int i = 0; i < 2; ++i)
        #pragma unroll
        for (int j = 0; j < 4; ++j){
            int r0 = i * 16 + g, r1 = r0 + 8;
            int cA = j * 8 + t4 * 2;
            *(float2*)&qs[r0 * 36 + cA] = make_float2(elu1(qacc[i][j][0]), elu1(qacc[i][j][1]));
            *(float2*)&qs[r1 * 36 + cA] = make_float2(elu1(qacc[i][j][2]), elu1(qacc[i][j][3]));
            *(float2*)&ks[r0 * 36 + cA] = make_float2(elu1(kacc[i][j][0]), elu1(kacc[i][j][1]));
            *(float2*)&ks[r1 * 36 + cA] = make_float2(elu1(kacc[i][j][2]), elu1(kacc[i][j][3]));
        }
    __syncwarp();

    {
        const float4* qr = (const float4*)&qs[lane * 36];
        const float4* kr = (const float4*)&ks[lane * 36];
        float sq = 0.f, sk = 0.f;
        #pragma unroll
        for (int m4 = 0; m4 < 8; ++m4){
            float4 a = qr[m4]; sq += a.x + a.y + a.z + a.w;
            float4 c2 = kr[m4]; sk += c2.x + c2.y + c2.z + c2.w;
        }
        atomicAdd(&qsS[c0 + lane], sq);   // smem atomic, 2 warps/addr
        atomicAdd(&ksS[c0 + lane], sk);
    }

    #pragma unroll 4
    for (int p = 0; p < 16; ++p){
        int idx = p * 32 + lane;
        int hh = idx >> 8, rem = idx & 255;
        int d = rem >> 4, e = rem & 15;
        const float4* qrow = (const float4*)&qs[(hh * 16 + d) * 36];
        const float4* krow = (const float4*)&ks[(hh * 16 + e) * 36];
        float acc = 0.f;
        #pragma unroll
        for (int m4 = 0; m4 < 8; ++m4){
            float4 a = qrow[m4], v = krow[m4];
            acc += a.x * v.x + a.y * v.y + a.z * v.z + a.w * v.w;
        }
        atomicAdd(&Asm[(cw * 2 + hh) * 256 + rem], acc);
    }
    __syncthreads();

    {
        size_t abase = ((size_t)(b * NMT + mt)) * 4096;
        for (int e2 = tid; e2 < 4096; e2 += 512) g_Apart[abase + e2] = Asm[e2];
        size_t qb = ((size_t)(b * NMT + mt)) * 512;
        g_QKpart[qb + tid] = (tid < 256) ? qsS[tid] : ksS[tid - 256];
    }
}

// ---------------------------------------------------------------------------
// Pass 2: reduce partials -> A[b], z; W2 = z(d)*A@wv, written as permuted tf32
// bits straight into g_W2P (so pass3 needs no conversion at all).
// NOTE reference broadcasting quirk: scale is z[b, d] (dh index), not z[b, h].
// ---------------------------------------------------------------------------
__global__ void pass2_kernel(const float* __restrict__ wv)
{
    __shared__ float As[4096];
    __shared__ float Qs[256], Ks[256], Z[16];
    const int b = blockIdx.x, tid = threadIdx.x;  // 512 threads

    for (int e = tid; e < 4096; e += 512){
        float s = 0.f;
        const float* p = g_Apart + (size_t)b * NMT * 4096 + e;
        for (int mt2 = 0; mt2 < NMT; ++mt2) s += p[(size_t)mt2 * 4096];
        As[e] = s;
    }
    {
        float s = 0.f;
        const float* p = g_QKpart + (size_t)b * NMT * 512 + tid;
        for (int mt2 = 0; mt2 < NMT; ++mt2) s += p[mt2 * 512];
        if (tid < 256) Qs[tid] = s; else Ks[tid - 256] = s;
    }
    __syncthreads();
    if (tid < 16){
        float dsum = 0.f;
        #pragma unroll
        for (int dd = 0; dd < 16; ++dd) dsum += Qs[tid * 16 + dd] * Ks[tid * 16 + dd];
        Z[tid] = 1.f / (dsum + 1e-6f);
    }
    __syncthreads();

    for (int idx = tid; idx < 65536; idx += 512){
        int c = idx >> 8, k = idx & 255;
        int h = c >> 4, d = c & 15;
        const float* arow = As + (h * 16 + d) * 16;
        float acc = 0.f;
        #pragma unroll
        for (int e = 0; e < 16; ++e) acc += arow[e] * wv[(h * 16 + e) * 256 + k];
        float val = Z[d] * acc;                         // z indexed by d (quirk)
        // permuted store
        int kt = k >> 4, kk8 = (k >> 3) & 1, t4 = k & 3, half = (k >> 2) & 1;
        int cw = c >> 5, i = (c >> 4) & 1, rr = c & 15;
        int gg = rr & 7, hi = (rr >> 3) & 1;
        int lane = gg * 4 + t4, e4 = hi + 2 * half;
        int pos = ((((kt * 8 + cw) * 2 + i) * 2 + kk8) * 32 + lane) * 4 + e4;
        g_W2P[(size_t)b * 65536 + pos] = f2tf32(val);
    }
}

// ---------------------------------------------------------------------------
// Pass 3: out[b] = W2[b] @ x[b]. CTA = 256c x 128m, 512 threads, warp tile
// 32x64. smem: W[2][4096]@0, X[2][16][136]@8192 -> 12544 fl = 50176 B.
// ---------------------------------------------------------------------------
__global__ void __launch_bounds__(512, 1) pass3_kernel(
    const float* __restrict__ x, float* __restrict__ out)
{
    extern __shared__ float sm[];
    const int tid  = threadIdx.x;
    const int warp = tid >> 5, lane = tid & 31;
    const int g = lane >> 2, t4 = lane & 3;
    const int cw = warp >> 1, mw = warp & 1;
    const int c0 = cw * 32, nbase = mw * 64;
    const int mt = blockIdx.x, b = blockIdx.y;
    const int m0 = mt * 128;

    float* Xss = sm + 8192;    // [2][16][136]

    const uint32_t* w2p = g_W2P + (size_t)b * 65536;
    const float* xb = x + (size_t)b * ((size_t)CIN * MM);
    const uint32_t smbase = (uint32_t)__cvta_generic_to_shared(sm);

    auto fill = [&](int st, int kt){
        const uint32_t* wsrc = w2p + kt * 4096;
        #pragma unroll
        for (int r = 0; r < 2; ++r){
            int chunk = tid + r * 512;
            cp16(smbase + (uint32_t)((st * 4096 + chunk * 4) * 4), wsrc + chunk * 4);
        }
        {
            int row = tid >> 5, j = tid & 31;   // 16 rows x 32 float4
            cp16(smbase + (uint32_t)((8192 + st * 2176 + row * 136 + j * 4) * 4),
                 xb + (size_t)(kt * 16 + row) * MM + m0 + j * 4);
        }
        cpcommit();
    };

    float pacc[2][8][4];
    #pragma unroll
    for (int i = 0; i < 2; ++i)
        #pragma unroll
        for (int j = 0; j < 8; ++j)
            #pragma unroll
            for (int e = 0; e < 4; ++e) pacc[i][j][e] = 0.f;

    fill(0, 0);

    for (int kt = 0; kt < 16; ++kt){
        int cur = kt & 1;
        if (kt + 1 < 16){
            fill(cur ^ 1, kt + 1);
            asm volatile("cp.async.wait_group 1;");
        } else {
            asm volatile("cp.async.wait_group 0;");
        }
        __syncthreads();

        const float* X_st = Xss + cur * 2176;
        // FIXED: cw stride within a 4096-word stage is 512 (was 1024 -> OOB garbage)
        const uint32_t wbase = cur * 4096 + cw * 512 + lane * 4;

        #pragma unroll
        for (int kk8 = 0; kk8 < 2; ++kk8){
            int kk = kk8 * 8;
            uint32_t aw[2][4], bx[8][2];
            #pragma unroll
            for (int i = 0; i < 2; ++i){
                uint32_t off = wbase + (uint32_t)((i * 2 + kk8) * 128);
                *(uint4*)aw[i] = *(const uint4*)((const uint32_t*)sm + off);
            }
            #pragma unroll
            for (int j = 0; j < 8; ++j){
                int n = nbase + j * 8 + g;
                bx[j][0] = f2tf32(X_st[(kk + t4) * 136 + n]);
                bx[j][1] = f2tf32(X_st[(kk + t4 + 4) * 136 + n]);
            }
            #pragma unroll
            for (int i = 0; i < 2; ++i)
                #pragma unroll
                for (int j = 0; j < 8; ++j)
                    mma8(pacc[i][j], aw[i], bx[j]);
        }
        __syncthreads();
    }

    // write out: out[b, c, m]
    #pragma unroll
    for (int i = 0; i < 2; ++i){
        size_t row0 = ((size_t)b * 256 + c0 + i * 16 + g) * MM + m0 + nbase;
        size_t row1 = row0 + (size_t)8 * MM;
        #pragma unroll
        for (int j = 0; j < 8; ++j){
            *(float2*)&out[row0 + j * 8 + t4 * 2] = make_float2(pacc[i][j][0], pacc[i][j][1]);
            *(float2*)&out[row1 + j * 8 + t4 * 2] = make_float2(pacc[i][j][2], pacc[i][j][3]);
        }
    }
}

extern "C" void kernel_launch(void* const* d_in, const int* in_sizes, int n_in,
                              void* d_out, int out_size)
{
    const float* x  = (const float*)d_in[0];
    const float* wq = (const float*)d_in[1];
    const float* wk = (const float*)d_in[2];
    const float* wv = (const float*)d_in[3];
    float* out = (float*)d_out;

    cudaFuncSetAttribute(pass1_kernel, cudaFuncAttributeMaxDynamicSharedMemorySize, 165888);
    cudaFuncSetAttribute(pass3_kernel, cudaFuncAttributeMaxDynamicSharedMemorySize, 50176);

    prep_w_kernel<<<256, 512>>>(wq, wk);
    pass1_kernel<<<dim3(NMT, BATCH), 512, 165888>>>(x);
    pass2_kernel<<<BATCH, 512>>>(wv);
    pass3_kernel<<<dim3(NMT3, BATCH), 512, 50176>>>(x, out);
}

// round 6
// speedup vs baseline: 1.3779x; 1.1393x over previous
#include <cuda_runtime.h>
#include <cstdint>

// Problem constants
constexpr int BATCH = 8;
constexpr int CIN   = 256;     // channels (K dim of GEMMs, also out channels)
constexpr int MM    = 16384;   // H*W
constexpr int NMT   = 256;     // MM / 64 m-tiles per batch (pass1)
constexpr int NMT3  = 128;     // MM / 128 m-tiles per batch (pass3)

// Scratch (static device arrays: allowed; no global atomics -> deterministic)
__device__ float    g_Apart[BATCH * NMT * 4096];   // per-(b,mtile) partial A
__device__ float    g_QKpart[BATCH * NMT * 512];   // per-(b,mtile) qsum/ksum partials
__device__ uint32_t g_WqP[65536];                  // wq, tf32 bits, fragment-permuted
__device__ uint32_t g_WkP[65536];                  // wk, tf32 bits, fragment-permuted
__device__ uint32_t g_W2P[BATCH * 65536];          // folded weight, tf32 bits, permuted

__device__ __forceinline__ uint32_t f2tf32(float x){
    uint32_t r; asm("cvt.rna.tf32.f32 %0, %1;" : "=r"(r) : "f"(x)); return r;
}
__device__ __forceinline__ void mma8(float c[4], const uint32_t a[4], const uint32_t b[2]){
    asm volatile("mma.sync.aligned.m16n8k8.row.col.f32.tf32.tf32.f32 "
        "{%0,%1,%2,%3},{%4,%5,%6,%7},{%8,%9},{%0,%1,%2,%3};"
        : "+f"(c[0]), "+f"(c[1]), "+f"(c[2]), "+f"(c[3])
        : "r"(a[0]), "r"(a[1]), "r"(a[2]), "r"(a[3]), "r"(b[0]), "r"(b[1]));
}
__device__ __forceinline__ void cp16(uint32_t dst, const void* src){
    asm volatile("cp.async.cg.shared.global [%0], [%1], 16;" :: "r"(dst), "l"(src));
}
__device__ __forceinline__ void cpcommit(){ asm volatile("cp.async.commit_group;"); }
__device__ __forceinline__ float elu1(float x){ return x > 0.f ? x + 1.f : __expf(x); }

// Fragment-permuted weight layout (per 256x256 matrix, 65536 entries):
//   pos = ((((kt*8 + cw)*2 + i)*2 + kk8)*32 + lane)*4 + e
//   g=lane>>2, t4=lane&3, hi=e&1, half=e>>1
//   r = cw*32 + i*16 + hi*8 + g ;  k = kt*16 + kk8*8 + half*4 + t4
// Within a kt-block (4096 words): cw stride = 512, i stride = 256, kk8 stride = 128.

// ---------------------------------------------------------------------------
// Prep: convert wq/wk (fp32 row-major [256][256]) -> tf32 bits, permuted.
// ---------------------------------------------------------------------------
__global__ void prep_w_kernel(const float* __restrict__ wq, const float* __restrict__ wk)
{
    int idx = blockIdx.x * 512 + threadIdx.x;      // grid 256 * 512 = 131072
    int mat = idx >> 16;
    int pos = idx & 65535;
    int e    = pos & 3;
    int lane = (pos >> 2) & 31;
    int kk8  = (pos >> 7) & 1;
    int i    = (pos >> 8) & 1;
    int cw   = (pos >> 9) & 7;
    int kt   = pos >> 12;
    int g = lane >> 2, t4 = lane & 3;
    int hi = e & 1, half = e >> 1;
    int r = cw * 32 + i * 16 + hi * 8 + g;
    int k = kt * 16 + kk8 * 8 + half * 4 + t4;
    const float* w = mat ? wk : wq;
    uint32_t* dst  = mat ? g_WkP : g_WqP;
    dst[pos] = f2tf32(w[r * 256 + k]);
}

// ---------------------------------------------------------------------------
// Pass 1: Q,K projection GEMMs (tf32 MMA, permuted weight fragments) + fused
// elu, then A computed with tensor-core MMAs (not scalar dots), qsum/ksum.
// CTA = 256c x 64m, 512 threads (16 warps: cw=warp>>1 channel block, mw m half)
// smem(floats): mainloop  WqS[2][4096]@0, WkS[2][4096]@8192, XS[2][16][72]@16384
//               epilogue  tiles[16][2304]@0 (reuse), AsmA[2][4096]@36864,
//                         qk[4][256]@45056  -> 46080 fl = 184320 B dynamic.
// ---------------------------------------------------------------------------
__global__ void __launch_bounds__(512, 1) pass1_kernel(const float* __restrict__ x)
{
    extern __shared__ float sm[];
    const int tid  = threadIdx.x;
    const int warp = tid >> 5, lane = tid & 31;
    const int g = lane >> 2, t4 = lane & 3;
    const int cw = warp >> 1, mw = warp & 1;
    const int nbase = mw * 32;
    const int mt = blockIdx.x, b = blockIdx.y;
    const int m0 = mt * 64;

    float* Xss   = sm + 16384;         // [2][16][72]
    float* tiles = sm;                 // epilogue reuse
    float* AsmA  = sm + 36864;         // [2][4096] split by mw
    float* qk    = sm + 45056;         // [4][256]: q(mw0),k(mw0),q(mw1),k(mw1) interleaved by mw*2

    const float* xb = x + (size_t)b * ((size_t)CIN * MM);
    const uint32_t smbase = (uint32_t)__cvta_generic_to_shared(sm);

    auto fill = [&](int st, int kt){
        const uint32_t* wqsrc = g_WqP + kt * 4096;
        const uint32_t* wksrc = g_WkP + kt * 4096;
        #pragma unroll
        for (int r = 0; r < 2; ++r){
            int chunk = tid + r * 512;       // 1024 x float4 per matrix
            cp16(smbase + (uint32_t)((st * 4096 + chunk * 4) * 4), wqsrc + chunk * 4);
            cp16(smbase + (uint32_t)((8192 + st * 4096 + chunk * 4) * 4), wksrc + chunk * 4);
        }
        if (tid < 256){
            int row = tid >> 4, j = tid & 15;
            cp16(smbase + (uint32_t)((16384 + st * 1152 + row * 72 + j * 4) * 4),
                 xb + (size_t)(kt * 16 + row) * MM + m0 + j * 4);
        }
        cpcommit();
    };

    float qacc[2][4][4], kacc[2][4][4];
    #pragma unroll
    for (int i = 0; i < 2; ++i)
        #pragma unroll
        for (int j = 0; j < 4; ++j)
            #pragma unroll
            for (int e = 0; e < 4; ++e){ qacc[i][j][e] = 0.f; kacc[i][j][e] = 0.f; }

    fill(0, 0);

    for (int kt = 0; kt < 16; ++kt){
        int cur = kt & 1;
        if (kt + 1 < 16){
            fill(cur ^ 1, kt + 1);
            asm volatile("cp.async.wait_group 1;");
        } else {
            asm volatile("cp.async.wait_group 0;");
        }
        __syncthreads();

        const float* X_st = Xss + cur * 1152;
        const uint32_t wbase = cur * 4096 + cw * 512 + lane * 4;

        #pragma unroll
        for (int kk8 = 0; kk8 < 2; ++kk8){
            int kk = kk8 * 8;
            uint32_t aq[2][4], ak[2][4], bx[4][2];
            #pragma unroll
            for (int i = 0; i < 2; ++i){
                uint32_t off = wbase + (uint32_t)((i * 2 + kk8) * 128);
                *(uint4*)aq[i] = *(const uint4*)((const uint32_t*)sm + off);
                *(uint4*)ak[i] = *(const uint4*)((const uint32_t*)sm + 8192 + off);
            }
            #pragma unroll
            for (int j = 0; j < 4; ++j){
                int n = nbase + j * 8 + g;
                bx[j][0] = f2tf32(X_st[(kk + t4) * 72 + n]);
                bx[j][1] = f2tf32(X_st[(kk + t4 + 4) * 72 + n]);
            }
            #pragma unroll
            for (int i = 0; i < 2; ++i)
                #pragma unroll
                for (int j = 0; j < 4; ++j){
                    mma8(qacc[i][j], aq[i], bx[j]);
                    mma8(kacc[i][j], ak[i], bx[j]);
                }
        }
        __syncthreads();
    }

    // ---- epilogue: elu+1, stage tiles [32 c][32 m] per warp ----
    float* qs = tiles + warp * 2304;   // [32][36]
    float* ks = qs + 1152;
    #pragma unroll
    for (int i = 0; i < 2; ++i)
        #pragma unroll
        for (int j = 0; j < 4; ++j){
            int r0 = i * 16 + g, r1 = r0 + 8;
            int cA = j * 8 + t4 * 2;
            *(float2*)&qs[r0 * 36 + cA] = make_float2(elu1(qacc[i][j][0]), elu1(qacc[i][j][1]));
            *(float2*)&qs[r1 * 36 + cA] = make_float2(elu1(qacc[i][j][2]), elu1(qacc[i][j][3]));
            *(float2*)&ks[r0 * 36 + cA] = make_float2(elu1(kacc[i][j][0]), elu1(kacc[i][j][1]));
            *(float2*)&ks[r1 * 36 + cA] = make_float2(elu1(kacc[i][j][2]), elu1(kacc[i][j][3]));
        }
    __syncwarp();

    // row sums over this warp's 32 m-columns (disjoint per-mw slots, no atomics)
    {
        const float4* qr = (const float4*)&qs[lane * 36];
        const float4* kr = (const float4*)&ks[lane * 36];
        float sq = 0.f, sk = 0.f;
        #pragma unroll
        for (int m4 = 0; m4 < 8; ++m4){
            float4 a = qr[m4]; sq += a.x + a.y + a.z + a.w;
            float4 c2 = kr[m4]; sk += c2.x + c2.y + c2.z + c2.w;
        }
        qk[(mw * 2 + 0) * 256 + cw * 32 + lane] = sq;
        qk[(mw * 2 + 1) * 256 + cw * 32 + lane] = sk;
    }

    // A partials via tensor cores: per head hh, A[d][e] += q[d,m] k[e,m] over m=32
    #pragma unroll
    for (int hh = 0; hh < 2; ++hh){
        float aacc[2][4];
        #pragma unroll
        for (int nh = 0; nh < 2; ++nh)
            #pragma unroll
            for (int e = 0; e < 4; ++e) aacc[nh][e] = 0.f;

        const float* qh = qs + (hh * 16) * 36;
        const float* kh = ks + (hh * 16) * 36;
        #pragma unroll
        for (int ms = 0; ms < 4; ++ms){
            int m = ms * 8;
            uint32_t afr[4], bfr[2][2];
            afr[0] = f2tf32(qh[g * 36 + m + t4]);
            afr[1] = f2tf32(qh[(g + 8) * 36 + m + t4]);
            afr[2] = f2tf32(qh[g * 36 + m + t4 + 4]);
            afr[3] = f2tf32(qh[(g + 8) * 36 + m + t4 + 4]);
            #pragma unroll
            for (int nh = 0; nh < 2; ++nh){
                bfr[nh][0] = f2tf32(kh[(nh * 8 + g) * 36 + m + t4]);
                bfr[nh][1] = f2tf32(kh[(nh * 8 + g) * 36 + m + t4 + 4]);
                mma8(aacc[nh], afr, bfr[nh]);
            }
        }
        // store to per-mw slab: AsmA[mw][head*256 + d*16 + e], each addr written once
        float* dst = AsmA + mw * 4096 + (cw * 2 + hh) * 256;
        #pragma unroll
        for (int nh = 0; nh < 2; ++nh){
            int e0 = nh * 8 + 2 * t4;
            *(float2*)&dst[g * 16 + e0]       = make_float2(aacc[nh][0], aacc[nh][1]);
            *(float2*)&dst[(g + 8) * 16 + e0] = make_float2(aacc[nh][2], aacc[nh][3]);
        }
    }
    __syncthreads();

    // write per-CTA partials (sum the two mw halves)
    {
        size_t abase = ((size_t)(b * NMT + mt)) * 4096;
        for (int e2 = tid; e2 < 4096; e2 += 512)
            g_Apart[abase + e2] = AsmA[e2] + AsmA[4096 + e2];
        size_t qb = ((size_t)(b * NMT + mt)) * 512;
        float v = (tid < 256) ? (qk[tid] + qk[512 + tid])
                              : (qk[tid] + qk[512 + tid]);  // k slots: 256..511 and 768..1023
        g_QKpart[qb + tid] = v;
    }
}

// ---------------------------------------------------------------------------
// Pass 2: reduce partials -> A[b], z; W2 = z(d)*A@wv, written as permuted tf32
// bits straight into g_W2P. NOTE reference broadcasting quirk: scale is
// z[b, d] (dh index), not z[b, h].
// ---------------------------------------------------------------------------
__global__ void pass2_kernel(const float* __restrict__ wv)
{
    __shared__ float As[4096];
    __shared__ float Qs[256], Ks[256], Z[16];
    const int b = blockIdx.x, tid = threadIdx.x;  // 512 threads

    for (int e = tid; e < 4096; e += 512){
        float s = 0.f;
        const float* p = g_Apart + (size_t)b * NMT * 4096 + e;
        for (int mt2 = 0; mt2 < NMT; ++mt2) s += p[(size_t)mt2 * 4096];
        As[e] = s;
    }
    {
        float s = 0.f;
        const float* p = g_QKpart + (size_t)b * NMT * 512 + tid;
        for (int mt2 = 0; mt2 < NMT; ++mt2) s += p[mt2 * 512];
        if (tid < 256) Qs[tid] = s; else Ks[tid - 256] = s;
    }
    __syncthreads();
    if (tid < 16){
        float dsum = 0.f;
        #pragma unroll
        for (int dd = 0; dd < 16; ++dd) dsum += Qs[tid * 16 + dd] * Ks[tid * 16 + dd];
        Z[tid] = 1.f / (dsum + 1e-6f);
    }
    __syncthreads();

    for (int idx = tid; idx < 65536; idx += 512){
        int c = idx >> 8, k = idx & 255;
        int h = c >> 4, d = c & 15;
        const float* arow = As + (h * 16 + d) * 16;
        float acc = 0.f;
        #pragma unroll
        for (int e = 0; e < 16; ++e) acc += arow[e] * wv[(h * 16 + e) * 256 + k];
        float val = Z[d] * acc;                         // z indexed by d (quirk)
        // permuted store
        int kt = k >> 4, kk8 = (k >> 3) & 1, t4 = k & 3, half = (k >> 2) & 1;
        int cw = c >> 5, i = (c >> 4) & 1, rr = c & 15;
        int gg = rr & 7, hi = (rr >> 3) & 1;
        int lane = gg * 4 + t4, e4 = hi + 2 * half;
        int pos = ((((kt * 8 + cw) * 2 + i) * 2 + kk8) * 32 + lane) * 4 + e4;
        g_W2P[(size_t)b * 65536 + pos] = f2tf32(val);
    }
}

// ---------------------------------------------------------------------------
// Pass 3: out[b] = W2[b] @ x[b]. CTA = 256c x 128m, 512 threads, warp tile
// 32x64. smem: W[2][4096]@0, X[2][16][136]@8192 -> 12544 fl = 50176 B.
// ---------------------------------------------------------------------------
__global__ void __launch_bounds__(512, 1) pass3_kernel(
    const float* __restrict__ x, float* __restrict__ out)
{
    extern __shared__ float sm[];
    const int tid  = threadIdx.x;
    const int warp = tid >> 5, lane = tid & 31;
    const int g = lane >> 2, t4 = lane & 3;
    const int cw = warp >> 1, mw = warp & 1;
    const int c0 = cw * 32, nbase = mw * 64;
    const int mt = blockIdx.x, b = blockIdx.y;
    const int m0 = mt * 128;

    float* Xss = sm + 8192;    // [2][16][136]

    const uint32_t* w2p = g_W2P + (size_t)b * 65536;
    const float* xb = x + (size_t)b * ((size_t)CIN * MM);
    const uint32_t smbase = (uint32_t)__cvta_generic_to_shared(sm);

    auto fill = [&](int st, int kt){
        const uint32_t* wsrc = w2p + kt * 4096;
        #pragma unroll
        for (int r = 0; r < 2; ++r){
            int chunk = tid + r * 512;
            cp16(smbase + (uint32_t)((st * 4096 + chunk * 4) * 4), wsrc + chunk * 4);
        }
        {
            int row = tid >> 5, j = tid & 31;   // 16 rows x 32 float4
            cp16(smbase + (uint32_t)((8192 + st * 2176 + row * 136 + j * 4) * 4),
                 xb + (size_t)(kt * 16 + row) * MM + m0 + j * 4);
        }
        cpcommit();
    };

    float pacc[2][8][4];
    #pragma unroll
    for (int i = 0; i < 2; ++i)
        #pragma unroll
        for (int j = 0; j < 8; ++j)
            #pragma unroll
            for (int e = 0; e < 4; ++e) pacc[i][j][e] = 0.f;

    fill(0, 0);

    for (int kt = 0; kt < 16; ++kt){
        int cur = kt & 1;
        if (kt + 1 < 16){
            fill(cur ^ 1, kt + 1);
            asm volatile("cp.async.wait_group 1;");
        } else {
            asm volatile("cp.async.wait_group 0;");
        }
        __syncthreads();

        const float* X_st = Xss + cur * 2176;
        const uint32_t wbase = cur * 4096 + cw * 512 + lane * 4;

        #pragma unroll
        for (int kk8 = 0; kk8 < 2; ++kk8){
            int kk = kk8 * 8;
            uint32_t aw[2][4], bx[8][2];
            #pragma unroll
            for (int i = 0; i < 2; ++i){
                uint32_t off = wbase + (uint32_t)((i * 2 + kk8) * 128);
                *(uint4*)aw[i] = *(const uint4*)((const uint32_t*)sm + off);
            }
            #pragma unroll
            for (int j = 0; j < 8; ++j){
                int n = nbase + j * 8 + g;
                bx[j][0] = f2tf32(X_st[(kk + t4) * 136 + n]);
                bx[j][1] = f2tf32(X_st[(kk + t4 + 4) * 136 + n]);
            }
            #pragma unroll
            for (int i = 0; i < 2; ++i)
                #pragma unroll
                for (int j = 0; j < 8; ++j)
                    mma8(pacc[i][j], aw[i], bx[j]);
        }
        __syncthreads();
    }

    // write out: out[b, c, m]
    #pragma unroll
    for (int i = 0; i < 2; ++i){
        size_t row0 = ((size_t)b * 256 + c0 + i * 16 + g) * MM + m0 + nbase;
        size_t row1 = row0 + (size_t)8 * MM;
        #pragma unroll
        for (int j = 0; j < 8; ++j){
            *(float2*)&out[row0 + j * 8 + t4 * 2] = make_float2(pacc[i][j][0], pacc[i][j][1]);
            *(float2*)&out[row1 + j * 8 + t4 * 2] = make_float2(pacc[i][j][2], pacc[i][j][3]);
        }
    }
}

extern "C" void kernel_launch(void* const* d_in, const int* in_sizes, int n_in,
                              void* d_out, int out_size)
{
    const float* x  = (const float*)d_in[0];
    const float* wq = (const float*)d_in[1];
    const float* wk = (const float*)d_in[2];
    const float* wv = (const float*)d_in[3];
    float* out = (float*)d_out;

    cudaFuncSetAttribute(pass1_kernel, cudaFuncAttributeMaxDynamicSharedMemorySize, 184320);
    cudaFuncSetAttribute(pass3_kernel, cudaFuncAttributeMaxDynamicSharedMemorySize, 50176);

    prep_w_kernel<<<256, 512>>>(wq, wk);
    pass1_kernel<<<dim3(NMT, BATCH), 512, 184320>>>(x);
    pass2_kernel<<<BATCH, 512>>>(wv);
    pass3_kernel<<<dim3(NMT3, BATCH), 512, 50176>>>(x, out);
}